// round 1
// baseline (speedup 1.0000x reference)
#include <cuda_runtime.h>
#include <math.h>

// ---------------------------------------------------------------------------
// AIO_DownsampleCouplingBlock: B=32, C=96, H=W=64, SPLIT1=48
//   x1 = x[:, :48], x2 = x[:, 48:]
//   a1 = conv(x1, w_hi, stride2, pad1)           -> (B,384,32,32)
//   y2 = down(x2) * exp(2*tanh(0.2*a1[:192])) + a1[192:]
//   a2 = conv(y2, w_lo, stride1, pad1)           -> (B,384,32,32)
//   y1 = down(x1) * exp(2*tanh(0.2*a2[:192])) + a2[192:]
//   out[b,o,h,w] = concat(y1,y2)[b,perm[o],h,w]*scale[perm[o]] + off[perm[o]]
//   scale = 0.2*softplus(0.5*act_norm)
// ---------------------------------------------------------------------------

#define NOUT 384

// scratch (device globals; no dynamic allocation allowed)
__device__ float g_a[32 * 384 * 32 * 32];      // a1, later reused for a2 (50.3MB)
__device__ float g_y2[32 * 192 * 32 * 32];     // y2 (tf32-rounded) (25.2MB)
__device__ float g_wpack[384 * 1728];          // packed weights [k][n] (2.65MB)
__device__ int   g_invperm[384];
__device__ float g_scale[384];

__device__ __forceinline__ unsigned f2tf32(float f) {
    unsigned u;
    asm("cvt.rna.tf32.f32 %0, %1;" : "=r"(u) : "f"(f));
    return u;
}

// ---------------------------------------------------------------------------
// prep: invert the one-hot permutation, precompute softplus scale
// ---------------------------------------------------------------------------
__global__ void prep_kernel(const float* __restrict__ perm_w,
                            const float* __restrict__ act_norm) {
    int p = threadIdx.x;
    if (p < 384) {
        int o_found = 0;
        for (int o = 0; o < 384; ++o)
            if (perm_w[o * 384 + p] > 0.5f) o_found = o;
        g_invperm[p] = o_found;   // out channel o takes concat channel p = perm[o]
        g_scale[p] = 0.2f * log1pf(expf(0.5f * act_norm[p]));
    }
}

// ---------------------------------------------------------------------------
// pack weights: OIHW w[n, c, kh, kw] -> g_wpack[(tap*CIN + c)*384 + n], tf32
// ---------------------------------------------------------------------------
__global__ void pack_kernel(const float* __restrict__ w, int cin) {
    int idx = blockIdx.x * 256 + threadIdx.x;
    int total = 384 * cin * 9;
    if (idx >= total) return;
    int n = idx % 384;
    int k = idx / 384;         // k = tap*cin + c
    int c = k % cin;
    int tap = k / cin;
    g_wpack[idx] = __uint_as_float(f2tf32(w[(n * cin + c) * 9 + tap]));
}

// ---------------------------------------------------------------------------
// implicit-GEMM conv via mma.sync m16n8k8 tf32
// M = 32768 pixels (b,h,w of 32x32 out), N = 384, K = CIN*9
// BM=128 (4 output rows of one image), BN=128, BK=16, 256 threads / 8 warps
// warp grid 2(M) x 4(N): warp tile 64x32, frags 4x4, acc 64 floats/thread
// ---------------------------------------------------------------------------
template <int CIN, int STRIDE, int HIN, int CTOT>
__global__ __launch_bounds__(256) void conv_gemm(
    const float* __restrict__ inp_param,
    const float* __restrict__ bias) {
    __shared__ float As[128 * 20];   // [m][k], row stride 20 -> conflict-free frags
    __shared__ float Bs[16 * 136];   // [k][n], row stride 136 -> conflict-free frags

    const float* inp = (CIN == 192) ? (const float*)g_y2 : inp_param;

    const int tid  = threadIdx.x;
    const int lane = tid & 31;
    const int warp = tid >> 5;
    const int wm = warp >> 2;   // 0..1
    const int wn = warp & 3;    // 0..3
    const int g4 = lane >> 2;   // 0..7
    const int t4 = lane & 3;    // 0..3

    const int bm   = blockIdx.x;       // 0..255
    const int bimg = bm >> 3;
    const int h0   = (bm & 7) * 4;     // 4 output rows per block
    const int n0   = blockIdx.y * 128;

    float acc[4][4][4];
#pragma unroll
    for (int i = 0; i < 4; i++)
#pragma unroll
        for (int j = 0; j < 4; j++)
#pragma unroll
            for (int k = 0; k < 4; k++) acc[i][j][k] = 0.f;

    for (int tap = 0; tap < 9; ++tap) {
        const int dh = tap / 3 - 1;
        const int dw = tap % 3 - 1;
        for (int c0 = 0; c0 < CIN; c0 += 16) {
            __syncthreads();
            // ---- load A tile: 128 pixels x 16 channels (coalesced along w)
#pragma unroll
            for (int j = 0; j < 2; ++j) {
                const int c = (tid >> 5) + 8 * j;
#pragma unroll
                for (int i = 0; i < 4; ++i) {
                    const int m = lane + 32 * i;
                    const int h = h0 + (m >> 5);
                    const int w = m & 31;
                    const int ih = h * STRIDE + dh;
                    const int iw = w * STRIDE + dw;
                    float v = 0.f;
                    if (ih >= 0 && ih < HIN && iw >= 0 && iw < HIN)
                        v = inp[((size_t)(bimg * CTOT + c0 + c) * HIN + ih) * HIN + iw];
                    As[m * 20 + c] = __uint_as_float(f2tf32(v));
                }
            }
            // ---- load B tile: 16 k-rows x 128 n (coalesced from packed)
#pragma unroll
            for (int j = 0; j < 2; ++j) {
                const int kk = (tid >> 5) + 8 * j;
                const int krow = tap * CIN + c0 + kk;
#pragma unroll
                for (int i = 0; i < 4; ++i) {
                    const int n = lane + 32 * i;
                    Bs[kk * 136 + n] = g_wpack[krow * 384 + n0 + n];
                }
            }
            __syncthreads();
            // ---- 2 x k8 MMA steps
#pragma unroll
            for (int ks = 0; ks < 2; ++ks) {
                const int k8 = ks * 8;
                unsigned af[4][4], bf[4][2];
#pragma unroll
                for (int mi = 0; mi < 4; ++mi) {
                    const int r = wm * 64 + mi * 16 + g4;
                    af[mi][0] = __float_as_uint(As[r * 20 + k8 + t4]);
                    af[mi][1] = __float_as_uint(As[(r + 8) * 20 + k8 + t4]);
                    af[mi][2] = __float_as_uint(As[r * 20 + k8 + t4 + 4]);
                    af[mi][3] = __float_as_uint(As[(r + 8) * 20 + k8 + t4 + 4]);
                }
#pragma unroll
                for (int ni = 0; ni < 4; ++ni) {
                    const int col = wn * 32 + ni * 8 + g4;
                    bf[ni][0] = __float_as_uint(Bs[(k8 + t4) * 136 + col]);
                    bf[ni][1] = __float_as_uint(Bs[(k8 + t4 + 4) * 136 + col]);
                }
#pragma unroll
                for (int mi = 0; mi < 4; ++mi)
#pragma unroll
                    for (int ni = 0; ni < 4; ++ni) {
                        asm volatile(
                            "mma.sync.aligned.m16n8k8.row.col.f32.tf32.tf32.f32 "
                            "{%0,%1,%2,%3}, {%4,%5,%6,%7}, {%8,%9}, {%0,%1,%2,%3};"
                            : "+f"(acc[mi][ni][0]), "+f"(acc[mi][ni][1]),
                              "+f"(acc[mi][ni][2]), "+f"(acc[mi][ni][3])
                            : "r"(af[mi][0]), "r"(af[mi][1]),
                              "r"(af[mi][2]), "r"(af[mi][3]),
                              "r"(bf[ni][0]), "r"(bf[ni][1]));
                    }
            }
        }
    }
    // ---- epilogue: add bias, store NCHW to g_a
#pragma unroll
    for (int mi = 0; mi < 4; ++mi) {
#pragma unroll
        for (int ni = 0; ni < 4; ++ni) {
            const int n = n0 + wn * 32 + ni * 8 + 2 * t4;
            const float b0v = bias[n];
            const float b1v = bias[n + 1];
#pragma unroll
            for (int rr = 0; rr < 2; ++rr) {
                const int m = wm * 64 + mi * 16 + g4 + rr * 8;
                const int h = h0 + (m >> 5);
                const int w = m & 31;
                size_t base = ((size_t)(bimg * 384 + n) * 32 + h) * 32 + w;
                g_a[base]        = acc[mi][ni][rr * 2 + 0] + b0v;
                g_a[base + 1024] = acc[mi][ni][rr * 2 + 1] + b1v;
            }
        }
    }
}

// ---------------------------------------------------------------------------
// affine1: y2 = down(x2)*exp(2*tanh(0.2*a1_lo)) + a1_hi
//   stores y2 (tf32-rounded, conv2 input) and final out channels sourced
//   from concat channel p = 192 + c.
// ---------------------------------------------------------------------------
__global__ void affine1_kernel(const float* __restrict__ x,
                               const float* __restrict__ act_offset,
                               float* __restrict__ outp) {
    int idx = blockIdx.x * 256 + threadIdx.x;
    if (idx >= 32 * 192 * 1024) return;
    const int hw = idx & 1023;
    const int t = idx >> 10;
    const int c = t % 192;
    const int b = t / 192;
    const int h = hw >> 5, w = hw & 31;

    const float lo = g_a[((size_t)(b * 384 + c) << 10) + hw];
    const float hi = g_a[((size_t)(b * 384 + c + 192) << 10) + hw];
    const int cc = c >> 2, ii = (c >> 1) & 1, jj = c & 1;
    const float xd = x[(((size_t)b * 96 + 48 + cc) * 64 + 2 * h + ii) * 64 + 2 * w + jj];
    const float y = xd * expf(2.0f * tanhf(0.2f * lo)) + hi;

    g_y2[((size_t)(b * 192 + c) << 10) + hw] = __uint_as_float(f2tf32(y));
    const int p = 192 + c;
    const int o = g_invperm[p];
    outp[((size_t)(b * 384 + o) << 10) + hw] = y * g_scale[p] + act_offset[p];
}

// ---------------------------------------------------------------------------
// affine2: y1 = down(x1)*exp(2*tanh(0.2*a2_lo)) + a2_hi -> out channels p = c
// ---------------------------------------------------------------------------
__global__ void affine2_kernel(const float* __restrict__ x,
                               const float* __restrict__ act_offset,
                               float* __restrict__ outp) {
    int idx = blockIdx.x * 256 + threadIdx.x;
    if (idx >= 32 * 192 * 1024) return;
    const int hw = idx & 1023;
    const int t = idx >> 10;
    const int c = t % 192;
    const int b = t / 192;
    const int h = hw >> 5, w = hw & 31;

    const float lo = g_a[((size_t)(b * 384 + c) << 10) + hw];
    const float hi = g_a[((size_t)(b * 384 + c + 192) << 10) + hw];
    const int cc = c >> 2, ii = (c >> 1) & 1, jj = c & 1;
    const float xd = x[(((size_t)b * 96 + cc) * 64 + 2 * h + ii) * 64 + 2 * w + jj];
    const float y = xd * expf(2.0f * tanhf(0.2f * lo)) + hi;

    const int o = g_invperm[c];
    outp[((size_t)(b * 384 + o) << 10) + hw] = y * g_scale[c] + act_offset[c];
}

// ---------------------------------------------------------------------------
extern "C" void kernel_launch(void* const* d_in, const int* in_sizes, int n_in,
                              void* d_out, int out_size) {
    const float* x          = (const float*)d_in[0];
    const float* w_hi       = (const float*)d_in[1];
    const float* b_hi       = (const float*)d_in[2];
    const float* w_lo       = (const float*)d_in[3];
    const float* b_lo       = (const float*)d_in[4];
    const float* act_norm   = (const float*)d_in[5];
    const float* act_offset = (const float*)d_in[6];
    const float* perm_w     = (const float*)d_in[7];
    float* out = (float*)d_out;

    prep_kernel<<<1, 384>>>(perm_w, act_norm);

    // conv1: CIN=48, stride 2, HIN=64, x has 96 channels (x1 = first 48)
    {
        int total = 384 * 48 * 9;
        pack_kernel<<<(total + 255) / 256, 256>>>(w_hi, 48);
    }
    conv_gemm<48, 2, 64, 96><<<dim3(256, 3), 256>>>(x, b_hi);

    {
        int total = 32 * 192 * 1024;
        affine1_kernel<<<(total + 255) / 256, 256>>>(x, act_offset, out);
    }

    // conv2: CIN=192, stride 1, HIN=32, input g_y2 (selected inside kernel)
    {
        int total = 384 * 192 * 9;
        pack_kernel<<<(total + 255) / 256, 256>>>(w_lo, 192);
    }
    conv_gemm<192, 1, 32, 192><<<dim3(256, 3), 256>>>(nullptr, b_lo);

    {
        int total = 32 * 192 * 1024;
        affine2_kernel<<<(total + 255) / 256, 256>>>(x, act_offset, out);
    }
}

// round 2
// speedup vs baseline: 1.4643x; 1.4643x over previous
#include <cuda_runtime.h>
#include <math.h>

// ---------------------------------------------------------------------------
// AIO_DownsampleCouplingBlock: B=32, C=96, H=W=64, SPLIT1=48
// Round 2: cp.async double-buffered tf32 implicit-GEMM.
// ---------------------------------------------------------------------------

// scratch (device globals; no dynamic allocation allowed)
__device__ float g_a[32 * 384 * 32 * 32];      // a1 / a2 (50.3MB)
__device__ float g_y2[32 * 192 * 32 * 32];     // y2 (tf32-rounded) (25.2MB)
__device__ float g_wpack1[384 * 432];          // packed w_hi [k][n]
__device__ float g_wpack2[384 * 1728];         // packed w_lo [k][n]
__device__ int   g_invperm[384];
__device__ float g_scale[384];

__device__ __forceinline__ unsigned f2tf32(float f) {
    unsigned u;
    asm("cvt.rna.tf32.f32 %0, %1;" : "=r"(u) : "f"(f));
    return u;
}

__device__ __forceinline__ void cp_async4(unsigned dst, const void* src, int sz) {
    asm volatile("cp.async.ca.shared.global [%0], [%1], 4, %2;\n"
                 :: "r"(dst), "l"(src), "r"(sz));
}
__device__ __forceinline__ void cp_async16(unsigned dst, const void* src) {
    asm volatile("cp.async.cg.shared.global [%0], [%1], 16;\n"
                 :: "r"(dst), "l"(src));
}

// ---------------------------------------------------------------------------
__global__ void prep_kernel(const float* __restrict__ perm_w,
                            const float* __restrict__ act_norm) {
    int p = threadIdx.x;
    if (p < 384) {
        int o_found = 0;
        for (int o = 0; o < 384; ++o)
            if (perm_w[o * 384 + p] > 0.5f) o_found = o;
        g_invperm[p] = o_found;
        g_scale[p] = 0.2f * log1pf(expf(0.5f * act_norm[p]));
    }
}

// pack OIHW w[n,c,kh,kw] -> dst[(tap*CIN + c)*384 + n], tf32-rounded
__global__ void pack_kernel(const float* __restrict__ w, int cin, int which) {
    float* dst = which ? g_wpack2 : g_wpack1;
    int idx = blockIdx.x * 256 + threadIdx.x;
    int total = 384 * cin * 9;
    if (idx >= total) return;
    int n = idx % 384;
    int k = idx / 384;
    int c = k % cin;
    int tap = k / cin;
    dst[idx] = __uint_as_float(f2tf32(w[(n * cin + c) * 9 + tap]));
}

// ---------------------------------------------------------------------------
// implicit-GEMM conv, m16n8k8 tf32 mma.sync, 2-stage cp.async pipeline
// M=32768 pixels, N=384, K=CIN*9.  BM=128, BN=128, BK=16.
// 256 thr / 8 warps, warp grid 2(M)x4(N), warp tile 64x32, acc 64 f/thread.
// A smem: [m][kperm] stride 24 (lds.64 frags, conflict-free)
// B smem: [k][n]     stride 136 (scalar frags, conflict-free)
// ---------------------------------------------------------------------------
template <int CIN, int STRIDE, int HIN, int CTOT>
__global__ __launch_bounds__(256) void conv_gemm(
    const float* __restrict__ inp_param,
    const float* __restrict__ bias) {
    __shared__ __align__(16) float As[2][128 * 24];
    __shared__ __align__(16) float Bs[2][16 * 136];

    const float* inp   = (CIN == 192) ? (const float*)g_y2 : inp_param;
    const float* wpack = (CIN == 192) ? (const float*)g_wpack2 : (const float*)g_wpack1;

    const int tid  = threadIdx.x;
    const int lane = tid & 31;
    const int warp = tid >> 5;
    const int wm = warp >> 2;
    const int wn = warp & 3;
    const int g4 = lane >> 2;
    const int t4 = lane & 3;

    const int bm   = blockIdx.x;
    const int bimg = bm >> 3;
    const int h0   = (bm & 7) * 4;
    const int n0   = blockIdx.y * 128;

    const unsigned sA0 = (unsigned)__cvta_generic_to_shared(&As[0][0]);
    const unsigned sA1 = (unsigned)__cvta_generic_to_shared(&As[1][0]);
    const unsigned sB0 = (unsigned)__cvta_generic_to_shared(&Bs[0][0]);
    const unsigned sB1 = (unsigned)__cvta_generic_to_shared(&Bs[1][0]);

    constexpr int TAPS_C = CIN / 16;
    constexpr int NIT = 9 * TAPS_C;

    float acc[4][4][4];
#pragma unroll
    for (int i = 0; i < 4; i++)
#pragma unroll
        for (int j = 0; j < 4; j++)
#pragma unroll
            for (int k = 0; k < 4; k++) acc[i][j][k] = 0.f;

    // ---- stage loader
    auto load_stage = [&](int it, int s) {
        const int tap = it / TAPS_C;
        const int c0  = (it - tap * TAPS_C) * 16;
        const int dh = tap / 3 - 1;
        const int dw = tap % 3 - 1;
        const unsigned aBase = s ? sA1 : sA0;
        const unsigned bBase = s ? sB1 : sB0;
        // A: 128 px x 16 ch, 8 x 4B cp.async / thread, k-permuted columns
#pragma unroll
        for (int j = 0; j < 2; ++j) {
            const int c = (tid >> 5) + 8 * j;
            const int col = (c & 8) | ((c & 3) << 1) | ((c >> 2) & 1);
            const float* srcb = inp + (size_t)(bimg * CTOT + c0 + c) * HIN * HIN;
#pragma unroll
            for (int i = 0; i < 4; ++i) {
                const int m = lane + 32 * i;
                const int h = h0 + (m >> 5);
                const int w = m & 31;
                const int ih = h * STRIDE + dh;
                const int iw = w * STRIDE + dw;
                const bool ok = (ih >= 0 && ih < HIN && iw >= 0 && iw < HIN);
                const float* src = ok ? (srcb + ih * HIN + iw) : inp;
                cp_async4(aBase + (unsigned)(m * 24 + col) * 4u, src, ok ? 4 : 0);
            }
        }
        // B: 16 k x 128 n, 2 x 16B cp.async / thread
        {
            const int kk = tid >> 4;
            const int nn = (tid & 15) * 8;
            const int krow = tap * CIN + c0 + kk;
            const float* src = wpack + (size_t)krow * 384 + n0 + nn;
            const unsigned dst = bBase + (unsigned)(kk * 136 + nn) * 4u;
            cp_async16(dst, src);
            cp_async16(dst + 16u, src + 4);
        }
    };

    load_stage(0, 0);
    asm volatile("cp.async.commit_group;\n");

#pragma unroll 1
    for (int it = 0; it < NIT; ++it) {
        const int s = it & 1;
        if (it + 1 < NIT) {
            load_stage(it + 1, s ^ 1);
            asm volatile("cp.async.commit_group;\n");
            asm volatile("cp.async.wait_group 1;\n");
        } else {
            asm volatile("cp.async.wait_group 0;\n");
        }
        __syncthreads();

        const float* AsS = As[s];
        const float* BsS = Bs[s];
#pragma unroll
        for (int ks = 0; ks < 2; ++ks) {
            float2 afr[4][2];
#pragma unroll
            for (int mi = 0; mi < 4; ++mi) {
                const int r = wm * 64 + mi * 16 + g4;
                afr[mi][0] = *(const float2*)&AsS[r * 24 + ks * 8 + 2 * t4];
                afr[mi][1] = *(const float2*)&AsS[(r + 8) * 24 + ks * 8 + 2 * t4];
            }
            float bfr[4][2];
#pragma unroll
            for (int ni = 0; ni < 4; ++ni) {
                const int col = wn * 32 + ni * 8 + g4;
                bfr[ni][0] = BsS[(ks * 8 + t4) * 136 + col];
                bfr[ni][1] = BsS[(ks * 8 + t4 + 4) * 136 + col];
            }
#pragma unroll
            for (int mi = 0; mi < 4; ++mi)
#pragma unroll
                for (int ni = 0; ni < 4; ++ni) {
                    asm volatile(
                        "mma.sync.aligned.m16n8k8.row.col.f32.tf32.tf32.f32 "
                        "{%0,%1,%2,%3}, {%4,%5,%6,%7}, {%8,%9}, {%0,%1,%2,%3};"
                        : "+f"(acc[mi][ni][0]), "+f"(acc[mi][ni][1]),
                          "+f"(acc[mi][ni][2]), "+f"(acc[mi][ni][3])
                        : "r"(__float_as_uint(afr[mi][0].x)),
                          "r"(__float_as_uint(afr[mi][1].x)),
                          "r"(__float_as_uint(afr[mi][0].y)),
                          "r"(__float_as_uint(afr[mi][1].y)),
                          "r"(__float_as_uint(bfr[ni][0])),
                          "r"(__float_as_uint(bfr[ni][1])));
                }
        }
        __syncthreads();
    }

    // ---- epilogue: add bias, store NCHW to g_a
#pragma unroll
    for (int mi = 0; mi < 4; ++mi) {
#pragma unroll
        for (int ni = 0; ni < 4; ++ni) {
            const int n = n0 + wn * 32 + ni * 8 + 2 * t4;
            const float b0v = bias[n];
            const float b1v = bias[n + 1];
#pragma unroll
            for (int rr = 0; rr < 2; ++rr) {
                const int m = wm * 64 + mi * 16 + g4 + rr * 8;
                const int h = h0 + (m >> 5);
                const int w = m & 31;
                size_t base = ((size_t)(bimg * 384 + n) * 32 + h) * 32 + w;
                g_a[base]        = acc[mi][ni][rr * 2 + 0] + b0v;
                g_a[base + 1024] = acc[mi][ni][rr * 2 + 1] + b1v;
            }
        }
    }
}

// ---------------------------------------------------------------------------
__global__ void affine1_kernel(const float* __restrict__ x,
                               const float* __restrict__ act_offset,
                               float* __restrict__ outp) {
    int idx = blockIdx.x * 256 + threadIdx.x;
    if (idx >= 32 * 192 * 1024) return;
    const int hw = idx & 1023;
    const int t = idx >> 10;
    const int c = t % 192;
    const int b = t / 192;
    const int h = hw >> 5, w = hw & 31;

    const float lo = g_a[((size_t)(b * 384 + c) << 10) + hw];
    const float hi = g_a[((size_t)(b * 384 + c + 192) << 10) + hw];
    const int cc = c >> 2, ii = (c >> 1) & 1, jj = c & 1;
    const float xd = x[(((size_t)b * 96 + 48 + cc) * 64 + 2 * h + ii) * 64 + 2 * w + jj];
    const float y = xd * expf(2.0f * tanhf(0.2f * lo)) + hi;

    g_y2[((size_t)(b * 192 + c) << 10) + hw] = __uint_as_float(f2tf32(y));
    const int p = 192 + c;
    const int o = g_invperm[p];
    outp[((size_t)(b * 384 + o) << 10) + hw] = y * g_scale[p] + act_offset[p];
}

__global__ void affine2_kernel(const float* __restrict__ x,
                               const float* __restrict__ act_offset,
                               float* __restrict__ outp) {
    int idx = blockIdx.x * 256 + threadIdx.x;
    if (idx >= 32 * 192 * 1024) return;
    const int hw = idx & 1023;
    const int t = idx >> 10;
    const int c = t % 192;
    const int b = t / 192;
    const int h = hw >> 5, w = hw & 31;

    const float lo = g_a[((size_t)(b * 384 + c) << 10) + hw];
    const float hi = g_a[((size_t)(b * 384 + c + 192) << 10) + hw];
    const int cc = c >> 2, ii = (c >> 1) & 1, jj = c & 1;
    const float xd = x[(((size_t)b * 96 + cc) * 64 + 2 * h + ii) * 64 + 2 * w + jj];
    const float y = xd * expf(2.0f * tanhf(0.2f * lo)) + hi;

    const int o = g_invperm[c];
    outp[((size_t)(b * 384 + o) << 10) + hw] = y * g_scale[c] + act_offset[c];
}

// ---------------------------------------------------------------------------
extern "C" void kernel_launch(void* const* d_in, const int* in_sizes, int n_in,
                              void* d_out, int out_size) {
    const float* x          = (const float*)d_in[0];
    const float* w_hi       = (const float*)d_in[1];
    const float* b_hi       = (const float*)d_in[2];
    const float* w_lo       = (const float*)d_in[3];
    const float* b_lo       = (const float*)d_in[4];
    const float* act_norm   = (const float*)d_in[5];
    const float* act_offset = (const float*)d_in[6];
    const float* perm_w     = (const float*)d_in[7];
    float* out = (float*)d_out;

    prep_kernel<<<1, 384>>>(perm_w, act_norm);
    pack_kernel<<<(384 * 48 * 9 + 255) / 256, 256>>>(w_hi, 48, 0);
    pack_kernel<<<(384 * 192 * 9 + 255) / 256, 256>>>(w_lo, 192, 1);

    conv_gemm<48, 2, 64, 96><<<dim3(256, 3), 256>>>(x, b_hi);

    {
        int total = 32 * 192 * 1024;
        affine1_kernel<<<(total + 255) / 256, 256>>>(x, act_offset, out);
    }

    conv_gemm<192, 1, 32, 192><<<dim3(256, 3), 256>>>(nullptr, b_lo);

    {
        int total = 32 * 192 * 1024;
        affine2_kernel<<<(total + 255) / 256, 256>>>(x, act_offset, out);
    }
}

// round 6
// speedup vs baseline: 2.1199x; 1.4477x over previous
#include <cuda_runtime.h>
#include <math.h>
#include <stdint.h>

// ---------------------------------------------------------------------------
// AIO_DownsampleCouplingBlock — Round 4: mma.sync tf32, conflict-free smem
// (tcgen05 unavailable: harness ptxas targets sm_103 plain, no 'a' features)
// ---------------------------------------------------------------------------

__device__ float g_a[32 * 384 * 1024];        // a1 / a2
__device__ float g_y2[32 * 192 * 1024];       // y2 (tf32-rounded)
__device__ float g_wp1[18 * 32 * 384];        // conv1 packed weights [st][k][n]
__device__ float g_wp2[54 * 32 * 384];        // conv2 packed weights [st][k][n]
__device__ int   g_invperm[384];
__device__ float g_scale[384];

__device__ __forceinline__ unsigned f2tf32(float f) {
    unsigned u;
    asm("cvt.rna.tf32.f32 %0, %1;" : "=r"(u) : "f"(f));
    return u;
}
__device__ __forceinline__ void cp_async4(unsigned dst, const void* src, int sz) {
    asm volatile("cp.async.ca.shared.global [%0], [%1], 4, %2;\n"
                 :: "r"(dst), "l"(src), "r"(sz));
}
__device__ __forceinline__ void cp_async16(unsigned dst, const void* src) {
    asm volatile("cp.async.cg.shared.global [%0], [%1], 16;\n"
                 :: "r"(dst), "l"(src));
}

// ---------------------------------------------------------------------------
__global__ void prep_kernel(const float* __restrict__ perm_w,
                            const float* __restrict__ act_norm) {
    int p = threadIdx.x;
    if (p < 384) {
        int o_found = 0;
        for (int o = 0; o < 384; ++o)
            if (perm_w[o * 384 + p] > 0.5f) o_found = o;
        g_invperm[p] = o_found;
        g_scale[p] = 0.2f * log1pf(expf(0.5f * act_norm[p]));
    }
}

// pack OIHW w[n,c,kh,kw] -> dst[st][k(32)][n(384)], st = tap*CH + cblk
// zero-padded in c beyond cin, tf32-rounded
__global__ void pack_kernel(const float* __restrict__ w, int cin, int CH, int which) {
    float* dst = which ? ((float*)g_wp2) : ((float*)g_wp1);
    int idx = blockIdx.x * 256 + threadIdx.x;
    int total = 9 * CH * 32 * 384;
    if (idx >= total) return;
    int n = idx % 384;
    int k = (idx / 384) & 31;
    int st = idx / (384 * 32);
    int tap = st / CH;
    int c = (st % CH) * 32 + k;
    float v = (c < cin) ? w[(n * cin + c) * 9 + tap] : 0.0f;
    dst[idx] = __uint_as_float(f2tf32(v));
}

// ---------------------------------------------------------------------------
// implicit-GEMM conv, m16n8k8 tf32 mma.sync, 2-stage cp.async, BK=32
// M=32768 px, N=384 (3 blocks x 128), K=CINP*9.
// A smem [k][m] stride 136  (coalesced 1-wavefront writes; conflict-free frags)
// B smem [k][n] stride 136  (16B coalesced writes; conflict-free frags)
// 256 thr / 8 warps, warp grid 2(M) x 4(N), warp tile 64x32, 64 acc/thread
// ---------------------------------------------------------------------------
#define STG 4352   // 32*136 floats per stage

template <int CIN, int CINP, int STRIDE, int HIN, int CTOT, int WHICH>
__global__ __launch_bounds__(256, 2) void conv_gemm(
    const float* __restrict__ inp_param,
    const float* __restrict__ bias) {
    extern __shared__ __align__(16) float smem[];
    float* As = smem;            // 2 stages
    float* Bs = smem + 2 * STG;  // 2 stages

    const float* inp = (WHICH == 2) ? (const float*)g_y2 : inp_param;
    const float* wp  = (WHICH == 2) ? (const float*)g_wp2 : (const float*)g_wp1;

    const int tid  = threadIdx.x;
    const int lane = tid & 31;
    const int warp = tid >> 5;
    const int wm = warp >> 2;
    const int wn = warp & 3;
    const int g4 = lane >> 2;
    const int t4 = lane & 3;

    const int bm   = blockIdx.x;
    const int bimg = bm >> 3;
    const int h0   = (bm & 7) * 4;
    const int n0   = blockIdx.y * 128;

    constexpr int CH  = CINP / 32;
    constexpr int NIT = 9 * CH;

    float acc[4][4][4];
#pragma unroll
    for (int i = 0; i < 4; i++)
#pragma unroll
        for (int j = 0; j < 4; j++)
#pragma unroll
            for (int k = 0; k < 4; k++) acc[i][j][k] = 0.f;

    auto load_stage = [&](int it, int s) {
        const int tap = it / CH;
        const int c0  = (it - tap * CH) * 32;
        const int dh = tap / 3 - 1;
        const int dw = tap % 3 - 1;
        const unsigned aB = (unsigned)__cvta_generic_to_shared(As + s * STG);
        const unsigned bB = (unsigned)__cvta_generic_to_shared(Bs + s * STG);
        // A: 32 ch-rows x 128 m, 16 x 4B cp.async / thread, coalesced in m
#pragma unroll
        for (int j = 0; j < 4; ++j) {
            const int k = warp + 8 * j;
            const int c = c0 + k;
            const bool cok = (c < CIN);
            const float* srcb = inp + (size_t)(bimg * CTOT + c) * HIN * HIN;
#pragma unroll
            for (int i = 0; i < 4; ++i) {
                const int m = lane + 32 * i;
                const int h = h0 + (m >> 5);
                const int w = m & 31;
                const int ih = h * STRIDE + dh;
                const int iw = w * STRIDE + dw;
                const bool ok = cok && ih >= 0 && ih < HIN && iw >= 0 && iw < HIN;
                const float* src = ok ? (srcb + ih * HIN + iw) : inp;
                cp_async4(aB + (unsigned)(k * 136 + m) * 4u, src, ok ? 4 : 0);
            }
        }
        // B: 32 k-rows x 128 n, 4 x 16B cp.async / thread, coalesced
        const float* wsrc = wp + (size_t)it * (32 * 384) + n0;
#pragma unroll
        for (int o = 0; o < 4; ++o) {
            const int idx = o * 256 + tid;
            const int k = idx >> 5;
            const int nl = (idx & 31) * 4;
            cp_async16(bB + (unsigned)(k * 136 + nl) * 4u, wsrc + k * 384 + nl);
        }
    };

    load_stage(0, 0);
    asm volatile("cp.async.commit_group;\n" ::: "memory");

#pragma unroll 1
    for (int it = 0; it < NIT; ++it) {
        const int s = it & 1;
        if (it + 1 < NIT) {
            load_stage(it + 1, s ^ 1);
            asm volatile("cp.async.commit_group;\n" ::: "memory");
            asm volatile("cp.async.wait_group 1;\n" ::: "memory");
        } else {
            asm volatile("cp.async.wait_group 0;\n" ::: "memory");
        }
        __syncthreads();

        const float* Ak = As + s * STG;
        const float* Bk = Bs + s * STG;
#pragma unroll
        for (int ks = 0; ks < 4; ++ks) {
            const int r0 = (ks * 8 + t4) * 136;
            const int r1 = (ks * 8 + t4 + 4) * 136;
            float af[4][4];
#pragma unroll
            for (int mi = 0; mi < 4; ++mi) {
                const int r = wm * 64 + mi * 16 + g4;
                af[mi][0] = Ak[r0 + r];
                af[mi][1] = Ak[r0 + r + 8];
                af[mi][2] = Ak[r1 + r];
                af[mi][3] = Ak[r1 + r + 8];
            }
            float bf[4][2];
#pragma unroll
            for (int ni = 0; ni < 4; ++ni) {
                const int col = wn * 32 + ni * 8 + g4;
                bf[ni][0] = Bk[r0 + col];
                bf[ni][1] = Bk[r1 + col];
            }
#pragma unroll
            for (int mi = 0; mi < 4; ++mi)
#pragma unroll
                for (int ni = 0; ni < 4; ++ni) {
                    asm volatile(
                        "mma.sync.aligned.m16n8k8.row.col.f32.tf32.tf32.f32 "
                        "{%0,%1,%2,%3}, {%4,%5,%6,%7}, {%8,%9}, {%0,%1,%2,%3};"
                        : "+f"(acc[mi][ni][0]), "+f"(acc[mi][ni][1]),
                          "+f"(acc[mi][ni][2]), "+f"(acc[mi][ni][3])
                        : "r"(__float_as_uint(af[mi][0])),
                          "r"(__float_as_uint(af[mi][1])),
                          "r"(__float_as_uint(af[mi][2])),
                          "r"(__float_as_uint(af[mi][3])),
                          "r"(__float_as_uint(bf[ni][0])),
                          "r"(__float_as_uint(bf[ni][1])));
                }
        }
        __syncthreads();
    }

    // epilogue: add bias, store NCHW to g_a
#pragma unroll
    for (int mi = 0; mi < 4; ++mi) {
#pragma unroll
        for (int ni = 0; ni < 4; ++ni) {
            const int n = n0 + wn * 32 + ni * 8 + 2 * t4;
            const float b0v = bias[n];
            const float b1v = bias[n + 1];
#pragma unroll
            for (int rr = 0; rr < 2; ++rr) {
                const int m = wm * 64 + mi * 16 + g4 + rr * 8;
                const int h = h0 + (m >> 5);
                const int w = m & 31;
                size_t base = ((size_t)(bimg * 384 + n) * 32 + h) * 32 + w;
                g_a[base]        = acc[mi][ni][rr * 2 + 0] + b0v;
                g_a[base + 1024] = acc[mi][ni][rr * 2 + 1] + b1v;
            }
        }
    }
}

// ---------------------------------------------------------------------------
// affine kernels: 2 channels (jj = 0,1) per thread -> contiguous float2 x read
// ---------------------------------------------------------------------------
template <int PHASE>
__global__ __launch_bounds__(256) void affine_kernel(const float* __restrict__ x,
                                                     const float* __restrict__ act_offset,
                                                     float* __restrict__ outp) {
    int idx = blockIdx.x * 256 + threadIdx.x;
    if (idx >= 32 * 96 * 1024) return;
    const int hw = idx & 1023;
    const int t = idx >> 10;
    const int cp = t % 96;
    const int b = t / 96;
    const int h = hw >> 5, w = hw & 31;
    const int c0 = 2 * cp;
    const int cc = cp >> 1, ii = cp & 1;
    const int xoff = (PHASE == 1) ? 48 : 0;

    const float lo0 = g_a[(((size_t)(b * 384 + c0)) << 10) + hw];
    const float lo1 = g_a[(((size_t)(b * 384 + c0 + 1)) << 10) + hw];
    const float hi0 = g_a[(((size_t)(b * 384 + c0 + 192)) << 10) + hw];
    const float hi1 = g_a[(((size_t)(b * 384 + c0 + 193)) << 10) + hw];
    const float2 xd = *(const float2*)&x[(((size_t)b * 96 + xoff + cc) * 64 + 2 * h + ii) * 64 + 2 * w];

    const float y0 = xd.x * expf(2.0f * tanhf(0.2f * lo0)) + hi0;
    const float y1 = xd.y * expf(2.0f * tanhf(0.2f * lo1)) + hi1;

    if (PHASE == 1) {
        g_y2[(((size_t)(b * 192 + c0)) << 10) + hw]     = __uint_as_float(f2tf32(y0));
        g_y2[(((size_t)(b * 192 + c0 + 1)) << 10) + hw] = __uint_as_float(f2tf32(y1));
        const int p0 = 192 + c0, p1 = 193 + c0;
        outp[(((size_t)(b * 384 + g_invperm[p0])) << 10) + hw] = y0 * g_scale[p0] + act_offset[p0];
        outp[(((size_t)(b * 384 + g_invperm[p1])) << 10) + hw] = y1 * g_scale[p1] + act_offset[p1];
    } else {
        const int p0 = c0, p1 = c0 + 1;
        outp[(((size_t)(b * 384 + g_invperm[p0])) << 10) + hw] = y0 * g_scale[p0] + act_offset[p0];
        outp[(((size_t)(b * 384 + g_invperm[p1])) << 10) + hw] = y1 * g_scale[p1] + act_offset[p1];
    }
}

// ---------------------------------------------------------------------------
extern "C" void kernel_launch(void* const* d_in, const int* in_sizes, int n_in,
                              void* d_out, int out_size) {
    const float* x          = (const float*)d_in[0];
    const float* w_hi       = (const float*)d_in[1];
    const float* b_hi       = (const float*)d_in[2];
    const float* w_lo       = (const float*)d_in[3];
    const float* b_lo       = (const float*)d_in[4];
    const float* act_norm   = (const float*)d_in[5];
    const float* act_offset = (const float*)d_in[6];
    const float* perm_w     = (const float*)d_in[7];
    float* out = (float*)d_out;

    const int SMEM_DYN = 4 * STG * 4;   // 69632 B

    static bool attr_done = false;
    cudaFuncSetAttribute(conv_gemm<48, 64, 2, 64, 96, 1>,
                         cudaFuncAttributeMaxDynamicSharedMemorySize, SMEM_DYN);
    cudaFuncSetAttribute(conv_gemm<192, 192, 1, 32, 192, 2>,
                         cudaFuncAttributeMaxDynamicSharedMemorySize, SMEM_DYN);
    (void)attr_done;

    prep_kernel<<<1, 384>>>(perm_w, act_norm);
    pack_kernel<<<(9 * 2 * 32 * 384 + 255) / 256, 256>>>(w_hi, 48, 2, 0);
    pack_kernel<<<(9 * 6 * 32 * 384 + 255) / 256, 256>>>(w_lo, 192, 6, 1);

    conv_gemm<48, 64, 2, 64, 96, 1><<<dim3(256, 3), 256, SMEM_DYN>>>(x, b_hi);

    {
        int total = 32 * 96 * 1024;
        affine_kernel<1><<<(total + 255) / 256, 256>>>(x, act_offset, out);
    }

    conv_gemm<192, 192, 1, 32, 192, 2><<<dim3(256, 3), 256, SMEM_DYN>>>(nullptr, b_lo);

    {
        int total = 32 * 96 * 1024;
        affine_kernel<2><<<(total + 255) / 256, 256>>>(x, act_offset, out);
    }
}